// round 6
// baseline (speedup 1.0000x reference)
#include <cuda_runtime.h>
#include <cuda_bf16.h>
#include <cstdint>
#include <math.h>

// Problem constants (fixed by the dataset)
#define NNODES 50000
#define FIN    256
#define HDIM   250
#define LDH    256          // padded row stride for all hidden buffers
#define EMAX   800000
#define ETOT   (EMAX + NNODES)

// ---------------- device scratch (no allocs allowed) ----------------
__device__ float g_h1[(size_t)NNODES * LDH];
__device__ float g_x1[(size_t)NNODES * LDH];
__device__ float g_hs[(size_t)NNODES * LDH];
__device__ float g_hd[(size_t)NNODES * LDH];
__device__ float g_w[ETOT];
__device__ float g_ssrc[NNODES];
__device__ float g_sdst[NNODES];
__device__ float g_rdenom[NNODES];
__device__ int   g_cnt[NNODES];
__device__ int   g_rowptr[NNODES + 1];
__device__ int   g_cursor[NNODES];
__device__ int   g_esrc[ETOT];

// ---------------- CSR build ----------------
__global__ void k_zero_cnt(int n) {
    int i = blockIdx.x * blockDim.x + threadIdx.x;
    if (i < n) g_cnt[i] = 0;
}

__global__ void k_hist(const int* __restrict__ ei, int E, int etot) {
    int e = blockIdx.x * blockDim.x + threadIdx.x;
    if (e >= etot) return;
    int d = (e < E) ? ei[E + e] : (e - E);
    atomicAdd(&g_cnt[d], 1);
}

__global__ void k_scan(int n) {
    __shared__ int partial[1024];
    int t = threadIdx.x;
    int chunk = (n + 1023) / 1024;
    int lo = t * chunk;
    int hi = lo + chunk; if (hi > n) hi = n;
    int s = 0;
    for (int i = lo; i < hi; ++i) s += g_cnt[i];
    partial[t] = s;
    __syncthreads();
    for (int off = 1; off < 1024; off <<= 1) {
        int v = (t >= off) ? partial[t - off] : 0;
        __syncthreads();
        partial[t] += v;
        __syncthreads();
    }
    int run = partial[t] - s;
    for (int i = lo; i < hi; ++i) {
        int c = g_cnt[i];
        g_rowptr[i] = run;
        g_cursor[i] = run;
        run += c;
    }
    if (t == 0) g_rowptr[n] = partial[1023];
}

__global__ void k_scatter(const int* __restrict__ ei, int E, int etot) {
    int e = blockIdx.x * blockDim.x + threadIdx.x;
    if (e >= etot) return;
    int s, d;
    if (e < E) { s = ei[e]; d = ei[E + e]; }
    else       { s = d = e - E; }
    int pos = atomicAdd(&g_cursor[d], 1);
    g_esrc[pos] = s;
}

// ---------------- BF16 split GEMM, ldmatrix-fed tensor cores ----------------
// C = A@B fp32-accurate: A = Ah+Al (bf16), B = Bh+Bl; C = AhBh + AlBh + AhBl.
__device__ __forceinline__ void bf16_split(float v, __nv_bfloat16& h, __nv_bfloat16& l) {
    h = __float2bfloat16(v);
    l = __float2bfloat16(v - __bfloat162float(h));
}

#define MMA_BF16(d, a, b) \
  asm volatile("mma.sync.aligned.m16n8k16.row.col.f32.bf16.bf16.f32 " \
      "{%0,%1,%2,%3},{%4,%5,%6,%7},{%8,%9},{%0,%1,%2,%3};" \
      : "+f"((d)[0]), "+f"((d)[1]), "+f"((d)[2]), "+f"((d)[3]) \
      : "r"((a)[0]), "r"((a)[1]), "r"((a)[2]), "r"((a)[3]), \
        "r"((b)[0]), "r"((b)[1]))

__device__ __forceinline__ void ldsm4(unsigned r[4], unsigned saddr) {
    asm volatile("ldmatrix.sync.aligned.m8n8.x4.shared.b16 {%0,%1,%2,%3}, [%4];"
                 : "=r"(r[0]), "=r"(r[1]), "=r"(r[2]), "=r"(r[3]) : "r"(saddr));
}
__device__ __forceinline__ void ldsm4t(unsigned r[4], unsigned saddr) {
    asm volatile("ldmatrix.sync.aligned.m8n8.x4.trans.shared.b16 {%0,%1,%2,%3}, [%4];"
                 : "=r"(r[0]), "=r"(r[1]), "=r"(r[2]), "=r"(r[3]) : "r"(saddr));
}

#define GBM 128
#define GBN 64
#define GBK 32
#define ASTR 40   // 80B rows: 8-row ldmatrix phases conflict-free
#define BSTR 72   // 144B rows: 8-row ldmatrix phases conflict-free

__global__ __launch_bounds__(256) void k_gemm_bf16s(
    const float* __restrict__ A, const float* __restrict__ B,
    float* __restrict__ C, int M, int Nn, int K, int lda, int ldb, int ldc)
{
    __shared__ __nv_bfloat16 As[2][GBM][ASTR];   // [hi|lo][m][k]
    __shared__ __nv_bfloat16 Bs[2][GBK][BSTR];   // [hi|lo][k][n]  (k-major)

    int tid  = threadIdx.x;
    int lane = tid & 31, warp = tid >> 5;
    int g = lane >> 2, tig = lane & 3;
    int warp_m = warp & 3, warp_n = warp >> 2;   // 4 x 2 warp grid
    int row0 = blockIdx.y * GBM;
    int col0 = blockIdx.x * GBN;
    int m_base = warp_m * 32, n_base = warp_n * 32;

    // ldmatrix lane-address components (constant over k-loop)
    int a_row = m_base + (lane & 15);            // + mt*16
    int a_kof = (lane >> 4) << 3;                // + ks
    int b_kof = (lane & 15);                     // + ks
    int b_col = n_base + ((lane >> 4) << 3);     // + pair*16

    float acc[2][4][4];
#pragma unroll
    for (int mt = 0; mt < 2; ++mt)
#pragma unroll
        for (int nt = 0; nt < 4; ++nt)
#pragma unroll
            for (int j = 0; j < 4; ++j) acc[mt][nt][j] = 0.f;

    for (int k0 = 0; k0 < K; k0 += GBK) {
        // ---- A tile fill: 128 x 32 floats, float4 LDG, bf16x2 STS ----
#pragma unroll
        for (int it = 0; it < 4; ++it) {
            int idx = tid + it * 256;          // 0..1023
            int r = idx >> 3, c4 = idx & 7;
            int gr = row0 + r;
            int gk = k0 + c4 * 4;
            float4 v = make_float4(0.f, 0.f, 0.f, 0.f);
            if (gr < M) {
                if (gk + 3 < K) {
                    v = *(const float4*)(A + (size_t)gr * lda + gk);
                } else {
                    float* p = (float*)&v;
#pragma unroll
                    for (int j = 0; j < 4; ++j)
                        if (gk + j < K) p[j] = A[(size_t)gr * lda + gk + j];
                }
            }
            __nv_bfloat16 h0, l0, h1, l1, h2, l2, h3, l3;
            bf16_split(v.x, h0, l0); bf16_split(v.y, h1, l1);
            bf16_split(v.z, h2, l2); bf16_split(v.w, h3, l3);
            *(__nv_bfloat162*)&As[0][r][c4 * 4    ] = __halves2bfloat162(h0, h1);
            *(__nv_bfloat162*)&As[0][r][c4 * 4 + 2] = __halves2bfloat162(h2, h3);
            *(__nv_bfloat162*)&As[1][r][c4 * 4    ] = __halves2bfloat162(l0, l1);
            *(__nv_bfloat162*)&As[1][r][c4 * 4 + 2] = __halves2bfloat162(l2, l3);
        }
        // ---- B tile fill: 32(k) x 64(n), float2 LDG (rows are 8B-aligned),
        //      k-major store, bf16x2 STS, conflict-free ----
#pragma unroll
        for (int it = 0; it < 4; ++it) {
            int idx = tid + it * 256;          // 0..1023
            int kk = idx >> 5, nn2 = idx & 31; // k row, n pair
            int gk = k0 + kk, gn = col0 + nn2 * 2;
            float2 v = make_float2(0.f, 0.f);
            if (gk < K) {
                if (gn + 1 < Nn) {
                    v = *(const float2*)(B + (size_t)gk * ldb + gn);
                } else if (gn < Nn) {
                    v.x = B[(size_t)gk * ldb + gn];
                }
            }
            __nv_bfloat16 h0, l0, h1, l1;
            bf16_split(v.x, h0, l0); bf16_split(v.y, h1, l1);
            *(__nv_bfloat162*)&Bs[0][kk][nn2 * 2] = __halves2bfloat162(h0, h1);
            *(__nv_bfloat162*)&Bs[1][kk][nn2 * 2] = __halves2bfloat162(l0, l1);
        }
        __syncthreads();

#pragma unroll
        for (int ks = 0; ks < GBK; ks += 16) {
            unsigned ah[2][4], al[2][4], bh[2][4], bl[2][4];
#pragma unroll
            for (int mt = 0; mt < 2; ++mt) {
                unsigned sa_h = (unsigned)__cvta_generic_to_shared(
                    &As[0][a_row + mt * 16][ks + a_kof]);
                unsigned sa_l = (unsigned)__cvta_generic_to_shared(
                    &As[1][a_row + mt * 16][ks + a_kof]);
                ldsm4(ah[mt], sa_h);
                ldsm4(al[mt], sa_l);
            }
#pragma unroll
            for (int p = 0; p < 2; ++p) {       // n-tile pairs (nt 0,1) and (2,3)
                unsigned sb_h = (unsigned)__cvta_generic_to_shared(
                    &Bs[0][ks + b_kof][b_col + p * 16]);
                unsigned sb_l = (unsigned)__cvta_generic_to_shared(
                    &Bs[1][ks + b_kof][b_col + p * 16]);
                ldsm4t(bh[p], sb_h);
                ldsm4t(bl[p], sb_l);
            }
#pragma unroll
            for (int mt = 0; mt < 2; ++mt)
#pragma unroll
                for (int nt = 0; nt < 4; ++nt) {
                    int p = nt >> 1, q = (nt & 1) * 2;
                    MMA_BF16(acc[mt][nt], ah[mt], &bh[p][q]);
                    MMA_BF16(acc[mt][nt], al[mt], &bh[p][q]);
                    MMA_BF16(acc[mt][nt], ah[mt], &bl[p][q]);
                }
        }
        __syncthreads();
    }

    // ---- epilogue ----
#pragma unroll
    for (int mt = 0; mt < 2; ++mt)
#pragma unroll
        for (int nt = 0; nt < 4; ++nt) {
            int r = row0 + m_base + mt * 16 + g;
            int c = col0 + n_base + nt * 8 + tig * 2;
            const float* d = acc[mt][nt];
            if (r < M) {
                if (c + 1 < Nn) *(float2*)&C[(size_t)r * ldc + c] = make_float2(d[0], d[1]);
                else if (c < Nn) C[(size_t)r * ldc + c] = d[0];
            }
            if (r + 8 < M) {
                if (c + 1 < Nn) *(float2*)&C[(size_t)(r + 8) * ldc + c] = make_float2(d[2], d[3]);
                else if (c < Nn) C[(size_t)(r + 8) * ldc + c] = d[2];
            }
        }
}

// ---------------- per-node attention scores: s = h . a ----------------
__global__ void k_scores(const float* __restrict__ hs, const float* __restrict__ hd,
                         const float* __restrict__ a_s, const float* __restrict__ a_d,
                         int n) {
    int warp = (blockIdx.x * blockDim.x + threadIdx.x) >> 5;
    int lane = threadIdx.x & 31;
    if (warp >= n) return;
    const float* rs = hs + (size_t)warp * LDH;
    const float* rd = hd + (size_t)warp * LDH;
    float s1 = 0.f, s2 = 0.f;
    for (int f = lane; f < HDIM; f += 32) {
        s1 += rs[f] * a_s[f];
        s2 += rd[f] * a_d[f];
    }
#pragma unroll
    for (int off = 16; off > 0; off >>= 1) {
        s1 += __shfl_xor_sync(0xffffffff, s1, off);
        s2 += __shfl_xor_sync(0xffffffff, s2, off);
    }
    if (lane == 0) { g_ssrc[warp] = s1; g_sdst[warp] = s2; }
}

// ---------------- segment softmax (warp per dst) ----------------
__global__ void k_attn(int n) {
    int v = (blockIdx.x * blockDim.x + threadIdx.x) >> 5;
    int lane = threadIdx.x & 31;
    if (v >= n) return;
    int beg = g_rowptr[v], end = g_rowptr[v + 1];
    float sd = g_sdst[v];
    float m = -1e30f;
    for (int j = beg + lane; j < end; j += 32) {
        float e = g_ssrc[g_esrc[j]] + sd;
        e = (e > 0.f) ? e : 0.2f * e;
        m = fmaxf(m, e);
    }
#pragma unroll
    for (int off = 16; off > 0; off >>= 1)
        m = fmaxf(m, __shfl_xor_sync(0xffffffff, m, off));
    float sum = 0.f;
    for (int j = beg + lane; j < end; j += 32) {
        float e = g_ssrc[g_esrc[j]] + sd;
        e = (e > 0.f) ? e : 0.2f * e;
        float w = expf(e - m);
        g_w[j] = w;
        sum += w;
    }
#pragma unroll
    for (int off = 16; off > 0; off >>= 1)
        sum += __shfl_xor_sync(0xffffffff, sum, off);
    if (lane == 0) g_rdenom[v] = 1.0f / sum;
}

// ---------------- weighted gather-accumulate (block per dst, float4) --------
__global__ __launch_bounds__(64) void k_agg(const float* __restrict__ hsrc,
                                            const float* __restrict__ bias,
                                            float* __restrict__ out,
                                            int ldo, int do_relu) {
    int v = blockIdx.x;
    int c4 = threadIdx.x;                    // 0..63 -> cols c4*4..c4*4+3
    int beg = g_rowptr[v], end = g_rowptr[v + 1];
    const float4* base = (const float4*)hsrc;
    float4 acc = make_float4(0.f, 0.f, 0.f, 0.f);

    int j = beg;
    float w_cur = 0.f; size_t off_cur = 0;
    if (j < end) { w_cur = g_w[j]; off_cur = (size_t)g_esrc[j] * (LDH / 4) + c4; }
    for (; j < end; ++j) {
        float w_nxt = 0.f; size_t off_nxt = 0;
        if (j + 1 < end) { w_nxt = g_w[j + 1]; off_nxt = (size_t)g_esrc[j + 1] * (LDH / 4) + c4; }
        float4 x = base[off_cur];
        acc.x = fmaf(w_cur, x.x, acc.x);
        acc.y = fmaf(w_cur, x.y, acc.y);
        acc.z = fmaf(w_cur, x.z, acc.z);
        acc.w = fmaf(w_cur, x.w, acc.w);
        w_cur = w_nxt; off_cur = off_nxt;
    }

    float rd = g_rdenom[v];
    float o[4] = {acc.x * rd, acc.y * rd, acc.z * rd, acc.w * rd};
    int c = c4 * 4;
#pragma unroll
    for (int jj = 0; jj < 4; ++jj) {
        int cc = c + jj;
        if (cc < HDIM) {
            float r = o[jj] + bias[cc];
            if (do_relu) r = fmaxf(r, 0.f);
            out[(size_t)v * ldo + cc] = r;
        } else if (ldo == LDH) {
            out[(size_t)v * ldo + cc] = 0.f;   // keep padding zero
        }
    }
}

// ---------------- launch ----------------
extern "C" void kernel_launch(void* const* d_in, const int* in_sizes, int n_in,
                              void* d_out, int out_size) {
    const float* x        = (const float*)d_in[0];
    const int*   ei       = (const int*)  d_in[1];
    const float* W1       = (const float*)d_in[2];
    const float* att_src1 = (const float*)d_in[3];
    const float* att_dst1 = (const float*)d_in[4];
    const float* b1       = (const float*)d_in[5];
    const float* W2s      = (const float*)d_in[6];
    const float* W2d      = (const float*)d_in[7];
    const float* att_src2 = (const float*)d_in[8];
    const float* att_dst2 = (const float*)d_in[9];
    const float* b2       = (const float*)d_in[10];
    float* out = (float*)d_out;

    const int n = in_sizes[0] / FIN;       // 50000
    const int E = in_sizes[1] / 2;         // 800000
    const int etot = E + n;

    float* h1; cudaGetSymbolAddress((void**)&h1, g_h1);
    float* x1; cudaGetSymbolAddress((void**)&x1, g_x1);
    float* hs; cudaGetSymbolAddress((void**)&hs, g_hs);
    float* hd; cudaGetSymbolAddress((void**)&hd, g_hd);

    dim3 gemm_grid((HDIM + GBN - 1) / GBN, (n + GBM - 1) / GBM);  // (4, 391)
    int sblocks = (n * 32 + 255) / 256;

    // --- CSR build interleaved with GEMM1 (GEMM1 has no CSR dependency) ---
    k_zero_cnt<<<(n + 255) / 256, 256>>>(n);
    k_hist<<<(etot + 255) / 256, 256>>>(ei, E, etot);
    k_scan<<<1, 1024>>>(n);
    k_gemm_bf16s<<<gemm_grid, 256>>>(x, W1, h1, n, HDIM, FIN, FIN, HDIM, LDH);
    k_scatter<<<(etot + 255) / 256, 256>>>(ei, E, etot);

    // --- layer 1 ---
    k_scores<<<sblocks, 256>>>(h1, h1, att_src1, att_dst1, n);
    k_attn<<<sblocks, 256>>>(n);
    k_agg<<<n, 64>>>(h1, b1, x1, LDH, 1);

    // --- layer 2 ---
    k_gemm_bf16s<<<gemm_grid, 256>>>(x1, W2s, hs, n, HDIM, HDIM, LDH, HDIM, LDH);
    k_gemm_bf16s<<<gemm_grid, 256>>>(x1, W2d, hd, n, HDIM, HDIM, LDH, HDIM, LDH);
    k_scores<<<sblocks, 256>>>(hs, hd, att_src2, att_dst2, n);
    k_attn<<<sblocks, 256>>>(n);
    k_agg<<<n, 64>>>(hs, b2, out, HDIM, 0);
}

// round 7
// speedup vs baseline: 1.5383x; 1.5383x over previous
#include <cuda_runtime.h>
#include <cuda_bf16.h>
#include <cstdint>
#include <math.h>

// Problem constants (fixed by the dataset)
#define NNODES 50000
#define FIN    256
#define HDIM   250
#define LDH    256          // padded row stride for all hidden buffers
#define EMAX   800000
#define ETOT   (EMAX + NNODES)

// ---------------- device scratch (no allocs allowed) ----------------
__device__ float g_h1[(size_t)NNODES * LDH];
__device__ float g_x1[(size_t)NNODES * LDH];
__device__ float g_hs[(size_t)NNODES * LDH];
__device__ float g_hd[(size_t)NNODES * LDH];
__device__ float g_w[ETOT];
__device__ float g_ssrc[NNODES];
__device__ float g_sdst[NNODES];
__device__ float g_rdenom[NNODES];
__device__ int   g_cnt[NNODES];
__device__ int   g_rowptr[NNODES + 1];
__device__ int   g_cursor[NNODES];
__device__ int   g_esrc[ETOT];

// ---------------- CSR build ----------------
__global__ void k_zero_cnt(int n) {
    int i = blockIdx.x * blockDim.x + threadIdx.x;
    if (i < n) g_cnt[i] = 0;
}

__global__ void k_hist(const int* __restrict__ ei, int E, int etot) {
    int e = blockIdx.x * blockDim.x + threadIdx.x;
    if (e >= etot) return;
    int d = (e < E) ? ei[E + e] : (e - E);
    atomicAdd(&g_cnt[d], 1);
}

__global__ void k_scan(int n) {
    __shared__ int partial[1024];
    int t = threadIdx.x;
    int chunk = (n + 1023) / 1024;
    int lo = t * chunk;
    int hi = lo + chunk; if (hi > n) hi = n;
    int s = 0;
    for (int i = lo; i < hi; ++i) s += g_cnt[i];
    partial[t] = s;
    __syncthreads();
    for (int off = 1; off < 1024; off <<= 1) {
        int v = (t >= off) ? partial[t - off] : 0;
        __syncthreads();
        partial[t] += v;
        __syncthreads();
    }
    int run = partial[t] - s;
    for (int i = lo; i < hi; ++i) {
        int c = g_cnt[i];
        g_rowptr[i] = run;
        g_cursor[i] = run;
        run += c;
    }
    if (t == 0) g_rowptr[n] = partial[1023];
}

__global__ void k_scatter(const int* __restrict__ ei, int E, int etot) {
    int e = blockIdx.x * blockDim.x + threadIdx.x;
    if (e >= etot) return;
    int s, d;
    if (e < E) { s = ei[e]; d = ei[E + e]; }
    else       { s = d = e - E; }
    int pos = atomicAdd(&g_cursor[d], 1);
    g_esrc[pos] = s;
}

// ---------------- BF16 split GEMM, ldmatrix + register-staged prefetch -------
// C = A@B fp32-accurate: A = Ah+Al (bf16), B = Bh+Bl; C = AhBh + AlBh + AhBl.
__device__ __forceinline__ void bf16_split(float v, __nv_bfloat16& h, __nv_bfloat16& l) {
    h = __float2bfloat16(v);
    l = __float2bfloat16(v - __bfloat162float(h));
}

#define MMA_BF16(d, a, b) \
  asm volatile("mma.sync.aligned.m16n8k16.row.col.f32.bf16.bf16.f32 " \
      "{%0,%1,%2,%3},{%4,%5,%6,%7},{%8,%9},{%0,%1,%2,%3};" \
      : "+f"((d)[0]), "+f"((d)[1]), "+f"((d)[2]), "+f"((d)[3]) \
      : "r"((a)[0]), "r"((a)[1]), "r"((a)[2]), "r"((a)[3]), \
        "r"((b)[0]), "r"((b)[1]))

__device__ __forceinline__ void ldsm4(unsigned r[4], unsigned saddr) {
    asm volatile("ldmatrix.sync.aligned.m8n8.x4.shared.b16 {%0,%1,%2,%3}, [%4];"
                 : "=r"(r[0]), "=r"(r[1]), "=r"(r[2]), "=r"(r[3]) : "r"(saddr));
}
__device__ __forceinline__ void ldsm4t(unsigned r[4], unsigned saddr) {
    asm volatile("ldmatrix.sync.aligned.m8n8.x4.trans.shared.b16 {%0,%1,%2,%3}, [%4];"
                 : "=r"(r[0]), "=r"(r[1]), "=r"(r[2]), "=r"(r[3]) : "r"(saddr));
}

#define GBM 128
#define GBN 64
#define GBK 32
#define ASTR 40   // 80B rows: ldmatrix phases +5 mod 8 -> conflict-free
#define BSTR 72   // 144B rows: ldmatrix phases +9 mod 8 -> conflict-free

__global__ __launch_bounds__(256, 2) void k_gemm_bf16s(
    const float* __restrict__ A, const float* __restrict__ B,
    float* __restrict__ C, int M, int Nn, int K, int lda, int ldb, int ldc)
{
    __shared__ __nv_bfloat16 As[2][GBM][ASTR];   // [hi|lo][m][k]
    __shared__ __nv_bfloat16 Bs[2][GBK][BSTR];   // [hi|lo][k][n]  (k-major)

    int tid  = threadIdx.x;
    int lane = tid & 31, warp = tid >> 5;
    int g = lane >> 2, tig = lane & 3;
    int warp_m = warp & 3, warp_n = warp >> 2;   // 4 x 2 warp grid
    int row0 = blockIdx.y * GBM;
    int col0 = blockIdx.x * GBN;
    int m_base = warp_m * 32, n_base = warp_n * 32;

    // per-thread staging indices (constant across k-tiles)
    int a_r  = tid >> 3;           // rows a_r, a_r handled with it-stride 32
    int a_c4 = tid & 7;
    int b_kk = tid >> 5;           // k rows b_kk + it*8
    int b_n2 = tid & 31;

    // ldmatrix lane-address components
    int lm_a_row = m_base + (lane & 15);
    int lm_a_kof = (lane >> 4) << 3;
    int lm_b_kof = (lane & 15);
    int lm_b_col = n_base + ((lane >> 4) << 3);

    float acc[2][4][4];
#pragma unroll
    for (int mt = 0; mt < 2; ++mt)
#pragma unroll
        for (int nt = 0; nt < 4; ++nt)
#pragma unroll
            for (int j = 0; j < 4; ++j) acc[mt][nt][j] = 0.f;

    float4 aS[4];
    float2 bS[4];
    const int ktiles = (K + GBK - 1) / GBK;

    // ---- LDG of tile t into registers ----
    auto ldg_tile = [&](int t) {
        int k0 = t * GBK;
#pragma unroll
        for (int it = 0; it < 4; ++it) {
            int r  = a_r + it * 32;
            int gr = row0 + r;
            int gk = k0 + a_c4 * 4;
            float4 v = make_float4(0.f, 0.f, 0.f, 0.f);
            if (gr < M) {
                if (gk + 3 < K) {
                    v = *(const float4*)(A + (size_t)gr * lda + gk);
                } else {
                    float* p = (float*)&v;
#pragma unroll
                    for (int j = 0; j < 4; ++j)
                        if (gk + j < K) p[j] = A[(size_t)gr * lda + gk + j];
                }
            }
            aS[it] = v;
        }
#pragma unroll
        for (int it = 0; it < 4; ++it) {
            int kk = b_kk + it * 8;
            int gk = k0 + kk, gn = col0 + b_n2 * 2;
            float2 v = make_float2(0.f, 0.f);
            if (gk < K) {
                if (gn + 1 < Nn) v = *(const float2*)(B + (size_t)gk * ldb + gn);
                else if (gn < Nn) v.x = B[(size_t)gk * ldb + gn];
            }
            bS[it] = v;
        }
    };

    // ---- convert + STS of staged registers ----
    auto sts_tile = [&]() {
#pragma unroll
        for (int it = 0; it < 4; ++it) {
            int r = a_r + it * 32;
            __nv_bfloat16 h0, l0, h1, l1, h2, l2, h3, l3;
            bf16_split(aS[it].x, h0, l0); bf16_split(aS[it].y, h1, l1);
            bf16_split(aS[it].z, h2, l2); bf16_split(aS[it].w, h3, l3);
            *(__nv_bfloat162*)&As[0][r][a_c4 * 4    ] = __halves2bfloat162(h0, h1);
            *(__nv_bfloat162*)&As[0][r][a_c4 * 4 + 2] = __halves2bfloat162(h2, h3);
            *(__nv_bfloat162*)&As[1][r][a_c4 * 4    ] = __halves2bfloat162(l0, l1);
            *(__nv_bfloat162*)&As[1][r][a_c4 * 4 + 2] = __halves2bfloat162(l2, l3);
        }
#pragma unroll
        for (int it = 0; it < 4; ++it) {
            int kk = b_kk + it * 8;
            __nv_bfloat16 h0, l0, h1, l1;
            bf16_split(bS[it].x, h0, l0); bf16_split(bS[it].y, h1, l1);
            *(__nv_bfloat162*)&Bs[0][kk][b_n2 * 2] = __halves2bfloat162(h0, h1);
            *(__nv_bfloat162*)&Bs[1][kk][b_n2 * 2] = __halves2bfloat162(l0, l1);
        }
    };

    // prologue: fill tile 0
    ldg_tile(0);
    sts_tile();
    __syncthreads();

    for (int t = 0; t < ktiles; ++t) {
        // prefetch next tile's globals while MMAs run on the current tile
        if (t + 1 < ktiles) ldg_tile(t + 1);

#pragma unroll
        for (int ks = 0; ks < GBK; ks += 16) {
            unsigned ah[2][4], al[2][4], bh[2][4], bl[2][4];
#pragma unroll
            for (int mt = 0; mt < 2; ++mt) {
                unsigned sa_h = (unsigned)__cvta_generic_to_shared(
                    &As[0][lm_a_row + mt * 16][ks + lm_a_kof]);
                unsigned sa_l = (unsigned)__cvta_generic_to_shared(
                    &As[1][lm_a_row + mt * 16][ks + lm_a_kof]);
                ldsm4(ah[mt], sa_h);
                ldsm4(al[mt], sa_l);
            }
#pragma unroll
            for (int p = 0; p < 2; ++p) {
                unsigned sb_h = (unsigned)__cvta_generic_to_shared(
                    &Bs[0][ks + lm_b_kof][lm_b_col + p * 16]);
                unsigned sb_l = (unsigned)__cvta_generic_to_shared(
                    &Bs[1][ks + lm_b_kof][lm_b_col + p * 16]);
                ldsm4t(bh[p], sb_h);
                ldsm4t(bl[p], sb_l);
            }
#pragma unroll
            for (int mt = 0; mt < 2; ++mt)
#pragma unroll
                for (int nt = 0; nt < 4; ++nt) {
                    int p = nt >> 1, q = (nt & 1) * 2;
                    MMA_BF16(acc[mt][nt], ah[mt], &bh[p][q]);
                    MMA_BF16(acc[mt][nt], al[mt], &bh[p][q]);
                    MMA_BF16(acc[mt][nt], ah[mt], &bl[p][q]);
                }
        }
        __syncthreads();             // all reads of smem tile done
        if (t + 1 < ktiles) {
            sts_tile();              // overwrite with prefetched tile
            __syncthreads();
        }
    }

    // ---- epilogue ----
#pragma unroll
    for (int mt = 0; mt < 2; ++mt)
#pragma unroll
        for (int nt = 0; nt < 4; ++nt) {
            int r = row0 + m_base + mt * 16 + g;
            int c = col0 + n_base + nt * 8 + tig * 2;
            const float* d = acc[mt][nt];
            if (r < M) {
                if (c + 1 < Nn) *(float2*)&C[(size_t)r * ldc + c] = make_float2(d[0], d[1]);
                else if (c < Nn) C[(size_t)r * ldc + c] = d[0];
            }
            if (r + 8 < M) {
                if (c + 1 < Nn) *(float2*)&C[(size_t)(r + 8) * ldc + c] = make_float2(d[2], d[3]);
                else if (c < Nn) C[(size_t)(r + 8) * ldc + c] = d[2];
            }
        }
}

// ---------------- per-node attention scores: s = h . a ----------------
__global__ void k_scores(const float* __restrict__ hs, const float* __restrict__ hd,
                         const float* __restrict__ a_s, const float* __restrict__ a_d,
                         int n) {
    int warp = (blockIdx.x * blockDim.x + threadIdx.x) >> 5;
    int lane = threadIdx.x & 31;
    if (warp >= n) return;
    const float* rs = hs + (size_t)warp * LDH;
    const float* rd = hd + (size_t)warp * LDH;
    float s1 = 0.f, s2 = 0.f;
    for (int f = lane; f < HDIM; f += 32) {
        s1 += rs[f] * a_s[f];
        s2 += rd[f] * a_d[f];
    }
#pragma unroll
    for (int off = 16; off > 0; off >>= 1) {
        s1 += __shfl_xor_sync(0xffffffff, s1, off);
        s2 += __shfl_xor_sync(0xffffffff, s2, off);
    }
    if (lane == 0) { g_ssrc[warp] = s1; g_sdst[warp] = s2; }
}

// ---------------- segment softmax (warp per dst) ----------------
__global__ void k_attn(int n) {
    int v = (blockIdx.x * blockDim.x + threadIdx.x) >> 5;
    int lane = threadIdx.x & 31;
    if (v >= n) return;
    int beg = g_rowptr[v], end = g_rowptr[v + 1];
    float sd = g_sdst[v];
    float m = -1e30f;
    for (int j = beg + lane; j < end; j += 32) {
        float e = g_ssrc[g_esrc[j]] + sd;
        e = (e > 0.f) ? e : 0.2f * e;
        m = fmaxf(m, e);
    }
#pragma unroll
    for (int off = 16; off > 0; off >>= 1)
        m = fmaxf(m, __shfl_xor_sync(0xffffffff, m, off));
    float sum = 0.f;
    for (int j = beg + lane; j < end; j += 32) {
        float e = g_ssrc[g_esrc[j]] + sd;
        e = (e > 0.f) ? e : 0.2f * e;
        float w = expf(e - m);
        g_w[j] = w;
        sum += w;
    }
#pragma unroll
    for (int off = 16; off > 0; off >>= 1)
        sum += __shfl_xor_sync(0xffffffff, sum, off);
    if (lane == 0) g_rdenom[v] = 1.0f / sum;
}

// ---------------- weighted gather-accumulate (block per dst, float4) --------
__global__ __launch_bounds__(64) void k_agg(const float* __restrict__ hsrc,
                                            const float* __restrict__ bias,
                                            float* __restrict__ out,
                                            int ldo, int do_relu) {
    int v = blockIdx.x;
    int c4 = threadIdx.x;                    // 0..63 -> cols c4*4..c4*4+3
    int beg = g_rowptr[v], end = g_rowptr[v + 1];
    const float4* base = (const float4*)hsrc;
    float4 acc = make_float4(0.f, 0.f, 0.f, 0.f);

    int j = beg;
    float w_cur = 0.f; size_t off_cur = 0;
    if (j < end) { w_cur = g_w[j]; off_cur = (size_t)g_esrc[j] * (LDH / 4) + c4; }
    for (; j < end; ++j) {
        float w_nxt = 0.f; size_t off_nxt = 0;
        if (j + 1 < end) { w_nxt = g_w[j + 1]; off_nxt = (size_t)g_esrc[j + 1] * (LDH / 4) + c4; }
        float4 x = base[off_cur];
        acc.x = fmaf(w_cur, x.x, acc.x);
        acc.y = fmaf(w_cur, x.y, acc.y);
        acc.z = fmaf(w_cur, x.z, acc.z);
        acc.w = fmaf(w_cur, x.w, acc.w);
        w_cur = w_nxt; off_cur = off_nxt;
    }

    float rd = g_rdenom[v];
    float o[4] = {acc.x * rd, acc.y * rd, acc.z * rd, acc.w * rd};
    int c = c4 * 4;
#pragma unroll
    for (int jj = 0; jj < 4; ++jj) {
        int cc = c + jj;
        if (cc < HDIM) {
            float r = o[jj] + bias[cc];
            if (do_relu) r = fmaxf(r, 0.f);
            out[(size_t)v * ldo + cc] = r;
        } else if (ldo == LDH) {
            out[(size_t)v * ldo + cc] = 0.f;   // keep padding zero
        }
    }
}

// ---------------- launch ----------------
extern "C" void kernel_launch(void* const* d_in, const int* in_sizes, int n_in,
                              void* d_out, int out_size) {
    const float* x        = (const float*)d_in[0];
    const int*   ei       = (const int*)  d_in[1];
    const float* W1       = (const float*)d_in[2];
    const float* att_src1 = (const float*)d_in[3];
    const float* att_dst1 = (const float*)d_in[4];
    const float* b1       = (const float*)d_in[5];
    const float* W2s      = (const float*)d_in[6];
    const float* W2d      = (const float*)d_in[7];
    const float* att_src2 = (const float*)d_in[8];
    const float* att_dst2 = (const float*)d_in[9];
    const float* b2       = (const float*)d_in[10];
    float* out = (float*)d_out;

    const int n = in_sizes[0] / FIN;       // 50000
    const int E = in_sizes[1] / 2;         // 800000
    const int etot = E + n;

    float* h1; cudaGetSymbolAddress((void**)&h1, g_h1);
    float* x1; cudaGetSymbolAddress((void**)&x1, g_x1);
    float* hs; cudaGetSymbolAddress((void**)&hs, g_hs);
    float* hd; cudaGetSymbolAddress((void**)&hd, g_hd);

    dim3 gemm_grid((HDIM + GBN - 1) / GBN, (n + GBM - 1) / GBM);  // (4, 391)
    int sblocks = (n * 32 + 255) / 256;

    // --- CSR build interleaved with GEMM1 (GEMM1 has no CSR dependency) ---
    k_zero_cnt<<<(n + 255) / 256, 256>>>(n);
    k_hist<<<(etot + 255) / 256, 256>>>(ei, E, etot);
    k_scan<<<1, 1024>>>(n);
    k_gemm_bf16s<<<gemm_grid, 256>>>(x, W1, h1, n, HDIM, FIN, FIN, HDIM, LDH);
    k_scatter<<<(etot + 255) / 256, 256>>>(ei, E, etot);

    // --- layer 1 ---
    k_scores<<<sblocks, 256>>>(h1, h1, att_src1, att_dst1, n);
    k_attn<<<sblocks, 256>>>(n);
    k_agg<<<n, 64>>>(h1, b1, x1, LDH, 1);

    // --- layer 2 ---
    k_gemm_bf16s<<<gemm_grid, 256>>>(x1, W2s, hs, n, HDIM, HDIM, LDH, HDIM, LDH);
    k_gemm_bf16s<<<gemm_grid, 256>>>(x1, W2d, hd, n, HDIM, HDIM, LDH, HDIM, LDH);
    k_scores<<<sblocks, 256>>>(hs, hd, att_src2, att_dst2, n);
    k_attn<<<sblocks, 256>>>(n);
    k_agg<<<n, 64>>>(hs, b2, out, HDIM, 0);
}